// round 10
// baseline (speedup 1.0000x reference)
#include <cuda_runtime.h>
#include <cuda_fp16.h>
#include <math.h>
#include <stdint.h>

// Problem constants
constexpr int T_ = 128, B_ = 32, L_ = 2, H_ = 1024, E_ = 1024, V_ = 32000;
constexpr int TB  = T_ * B_;     // 4096
constexpr int G4H = 4 * H_;      // 4096

constexpr int NBLK = 128;        // persistent blocks (LSTM), 8 units each

// fp16 GEMM constants
constexpr int K2 = 2048;         // 2-term augmented K
constexpr int GEMM_STAGE = 49152;            // A 16KB + B 32KB
constexpr int GEMM_SMEM  = 3 * GEMM_STAGE;   // 147456

// LSTM smem: W_hi (16 chunks x 4KB) + 4 h slots x 8KB
constexpr int LSTM_SMEM = 16 * 4096 + 4 * 8192;   // 98304

// Scratch (device globals)
__device__ float g_xproj[TB * G4H];
__device__ alignas(256) __half g_embaug[(size_t)TB * K2];        // 16.8MB
__device__ alignas(256) __half g_y0aug[(size_t)TB * K2];         // 16.8MB
__device__ alignas(256) __half g_y1aug[(size_t)TB * K2];         // 16.8MB
__device__ alignas(256) __half g_augwih[(size_t)L_ * G4H * K2];  // 33.5MB
__device__ alignas(256) __half g_augdec[(size_t)V_ * K2];        // 131MB
__device__ alignas(256) __half g_whhaug[(size_t)L_ * G4H * H_];  // 16MB (hi only)
__device__ alignas(256) __half g_h0aug[B_ * K2];                 // [32][2048] hi

// barrier state: padded per-block monotonic flags
__device__ unsigned g_flags[NBLK * 32];

// ---------------------------------------------------------------------------
// Embedding gather + fp16 hi/lo split: out[tb] = [hi(emb[v]) | lo(emb[v])]
// ---------------------------------------------------------------------------
__global__ void embed_aug_kernel(const int* __restrict__ idx,
                                 const float* __restrict__ emb,
                                 __half* __restrict__ out) {
    int tb = blockIdx.x;
    int v  = idx[tb];
    int k4 = threadIdx.x << 2;
    float4 x = *(const float4*)(emb + (size_t)v * E_ + k4);
    float xs[4] = {x.x, x.y, x.z, x.w};
    __half h[4], l[4];
#pragma unroll
    for (int j = 0; j < 4; j++) {
        h[j] = __float2half_rn(xs[j]);
        l[j] = __float2half_rn(xs[j] - __half2float(h[j]));
    }
    unsigned long long hv, lv;
    unsigned short* hp = (unsigned short*)&hv;
    unsigned short* lp = (unsigned short*)&lv;
#pragma unroll
    for (int j = 0; j < 4; j++) {
        hp[j] = *(unsigned short*)&h[j];
        lp[j] = *(unsigned short*)&l[j];
    }
    __half* base = out + (size_t)tb * K2 + k4;
    *(unsigned long long*)(base)        = hv;
    *(unsigned long long*)(base + 1024) = lv;
}

// ---------------------------------------------------------------------------
// Weight augmentation: fp32 [rows][1024] -> fp16 [rows][2048] = [hi|hi]
// ---------------------------------------------------------------------------
__global__ void augw_kernel(const float* __restrict__ in,
                            __half* __restrict__ out) {
    int r  = blockIdx.x;
    int k4 = threadIdx.x << 2;
    float4 x = *(const float4*)(in + (size_t)r * 1024 + k4);
    float xs[4] = {x.x, x.y, x.z, x.w};
    __half h[4];
#pragma unroll
    for (int j = 0; j < 4; j++) h[j] = __float2half_rn(xs[j]);
    unsigned long long hv;
    unsigned short* hp = (unsigned short*)&hv;
#pragma unroll
    for (int j = 0; j < 4; j++) hp[j] = *(unsigned short*)&h[j];
    __half* base = out + (size_t)r * K2 + k4;
    *(unsigned long long*)(base)        = hv;
    *(unsigned long long*)(base + 1024) = hv;
}

// W_hh hi-plane only: fp32 [L*4H][1024] -> fp16 [L*4H][1024]
__global__ void whh_aug_kernel(const float* __restrict__ Whh,
                               __half* __restrict__ out) {
    int row = blockIdx.x;
    int k = threadIdx.x << 2;
    float4 v = *(const float4*)(Whh + (size_t)row * 1024 + k);
    __half h[4] = {__float2half_rn(v.x), __float2half_rn(v.y),
                   __float2half_rn(v.z), __float2half_rn(v.w)};
    unsigned long long hv;
    unsigned short* hp = (unsigned short*)&hv;
#pragma unroll
    for (int j = 0; j < 4; j++) hp[j] = *(unsigned short*)&h[j];
    *(unsigned long long*)(out + (size_t)row * 1024 + k) = hv;
}

// h0 -> fp16 hi into h0aug [32][2048] (hi cols only)
__global__ void h0_aug_kernel(const float* __restrict__ h0l,
                              __half* __restrict__ h0aug) {
    int b = blockIdx.x;
    int k = threadIdx.x << 2;
    float4 v = *(const float4*)(h0l + (size_t)b * H_ + k);
    __half h[4] = {__float2half_rn(v.x), __float2half_rn(v.y),
                   __float2half_rn(v.z), __float2half_rn(v.w)};
    unsigned long long hv;
    unsigned short* hp = (unsigned short*)&hv;
#pragma unroll
    for (int j = 0; j < 4; j++) hp[j] = *(unsigned short*)&h[j];
    *(unsigned long long*)(h0aug + (size_t)b * K2 + k) = hv;
}

// ---------------------------------------------------------------------------
// low-level helpers
// ---------------------------------------------------------------------------
__device__ __forceinline__ uint32_t smem_u32(const void* p) {
    uint32_t a;
    asm("{ .reg .u64 t; cvta.to.shared.u64 t, %1; cvt.u32.u64 %0, t; }"
        : "=r"(a) : "l"(p));
    return a;
}
__device__ __forceinline__ void cp_async16(uint32_t saddr, const void* gptr) {
    asm volatile("cp.async.cg.shared.global [%0], [%1], 16;\n"
                 :: "r"(saddr), "l"(gptr));
}
__device__ __forceinline__ void cp_commit() {
    asm volatile("cp.async.commit_group;\n");
}
template <int N>
__device__ __forceinline__ void cp_wait() {
    asm volatile("cp.async.wait_group %0;\n" :: "n"(N));
}
__device__ __forceinline__ void ldsm4a(uint32_t* r, uint32_t a) {
    asm volatile("ldmatrix.sync.aligned.m8n8.x4.shared.b16 {%0,%1,%2,%3},[%4];"
                 : "=r"(r[0]), "=r"(r[1]), "=r"(r[2]), "=r"(r[3]) : "r"(a));
}
__device__ __forceinline__ void mma16816(float* c, const uint32_t* a,
                                         uint32_t b0, uint32_t b1) {
    asm volatile(
        "mma.sync.aligned.m16n8k16.row.col.f32.f16.f16.f32 "
        "{%0,%1,%2,%3},{%4,%5,%6,%7},{%8,%9},{%0,%1,%2,%3};"
        : "+f"(c[0]), "+f"(c[1]), "+f"(c[2]), "+f"(c[3])
        : "r"(a[0]), "r"(a[1]), "r"(a[2]), "r"(a[3]), "r"(b0), "r"(b1));
}
__device__ __forceinline__ float sigf(float x) { return 1.f / (1.f + expf(-x)); }

// ---------------------------------------------------------------------------
// fp16 mma.sync GEMM: C[4096, N] = A @ B^T + bias1 + bias2
// 128x256 block tile, 64x64 warp tile, BK=64 halves, 3-stage cp.async.
// grid.x = 32 * (N/256); bm = bid & 31, bn = bid >> 5.
// ---------------------------------------------------------------------------
__global__ __launch_bounds__(256, 1)
void gemm_fp16_mma(const __half* __restrict__ A, const __half* __restrict__ B,
                   const float* __restrict__ bias1, const float* __restrict__ bias2,
                   float* __restrict__ C, int K, int ldc) {
    extern __shared__ char sm[];
    const int tid  = threadIdx.x;
    const int lane = tid & 31;
    const int wid  = tid >> 5;
    const int bm   = blockIdx.x & 31;
    const int bn   = blockIdx.x >> 5;
    const int wm   = wid >> 2;    // 0..1  -> 64 rows
    const int wn   = wid & 3;     // 0..3  -> 64 cols
    const uint32_t smb = smem_u32(sm);
    const int KT = K >> 6;

    const __half* Ag = A + (size_t)(bm * 128) * K;
    const __half* Bg = B + (size_t)(bn * 256) * K;

    auto issue = [&](int kt, int st) {
        uint32_t sa = smb + st * GEMM_STAGE;
#pragma unroll
        for (int j = 0; j < 4; j++) {             // A: 128 rows
            int id  = tid + j * 256;
            int row = id >> 3, c = id & 7;
            uint32_t dst = sa + (uint32_t)(row * 128 + ((c ^ (row & 7)) << 4));
            cp_async16(dst, Ag + (size_t)row * K + kt * 64 + c * 8);
        }
#pragma unroll
        for (int j = 0; j < 8; j++) {             // B: 256 rows
            int id  = tid + j * 256;
            int row = id >> 3, c = id & 7;
            uint32_t dst = sa + 16384u
                         + (uint32_t)(row * 128 + ((c ^ (row & 7)) << 4));
            cp_async16(dst, Bg + (size_t)row * K + kt * 64 + c * 8);
        }
        cp_commit();
    };

    float acc[4][8][4];
#pragma unroll
    for (int i = 0; i < 4; i++)
#pragma unroll
        for (int j = 0; j < 8; j++)
#pragma unroll
            for (int k = 0; k < 4; k++) acc[i][j][k] = 0.f;

    issue(0, 0);
    issue(1, 1);

    const int l7  = lane & 7;
    const int l8  = (lane >> 3) & 1;
    const int l16 = lane >> 4;

    uint32_t aRow[4], bRowP[4];
#pragma unroll
    for (int mt = 0; mt < 4; mt++)
        aRow[mt] = (uint32_t)((wm * 64 + mt * 16 + l7 + l8 * 8) * 128);
#pragma unroll
    for (int p = 0; p < 4; p++)
        bRowP[p] = (uint32_t)(16384 + (wn * 64 + p * 16 + l16 * 8 + l7) * 128);

    for (int kt = 0; kt < KT; kt++) {
        if (kt + 1 < KT) cp_wait<1>(); else cp_wait<0>();
        __syncthreads();
        if (kt + 2 < KT) issue(kt + 2, (kt + 2) % 3);

        uint32_t st = smb + (kt % 3) * GEMM_STAGE;
#pragma unroll
        for (int kq = 0; kq < 4; kq++) {
            uint32_t aF[4][4], bQ[4][4];
            uint32_t ach = (uint32_t)((((kq * 2 + l16) ^ l7)) << 4);
#pragma unroll
            for (int mt = 0; mt < 4; mt++)
                ldsm4a(aF[mt], st + aRow[mt] + ach);
            uint32_t bch = (uint32_t)((((kq * 2 + l8) ^ l7)) << 4);
#pragma unroll
            for (int p = 0; p < 4; p++)
                ldsm4a(bQ[p], st + bRowP[p] + bch);
#pragma unroll
            for (int mt = 0; mt < 4; mt++)
#pragma unroll
                for (int nt = 0; nt < 8; nt++)
                    mma16816(acc[mt][nt], aF[mt],
                             bQ[nt >> 1][(nt & 1) * 2],
                             bQ[nt >> 1][(nt & 1) * 2 + 1]);
        }
    }

    const int gid = lane >> 2, tig = lane & 3;
#pragma unroll
    for (int mt = 0; mt < 4; mt++) {
        int row0 = bm * 128 + wm * 64 + mt * 16 + gid;
#pragma unroll
        for (int nt = 0; nt < 8; nt++) {
            int col = bn * 256 + wn * 64 + nt * 8 + tig * 2;
            float b0 = bias1 ? bias1[col] : 0.f;
            float b1 = bias1 ? bias1[col + 1] : 0.f;
            if (bias2) { b0 += bias2[col]; b1 += bias2[col + 1]; }
            *(float2*)(C + (size_t)row0 * ldc + col) =
                make_float2(acc[mt][nt][0] + b0, acc[mt][nt][1] + b1);
            *(float2*)(C + (size_t)(row0 + 8) * ldc + col) =
                make_float2(acc[mt][nt][2] + b0, acc[mt][nt][3] + b1);
        }
    }
}

// ---------------------------------------------------------------------------
// Persistent LSTM: gates = h_hi @ W_hi^T.
// h stream reads straight from yaug rows (stride K2); t=0 from h0aug.
// Output h written ONLY as [hi|lo] rows of yaug (GEMM-A layout).
// ---------------------------------------------------------------------------
__global__ __launch_bounds__(256, 1)
void lstm_mma(const float* __restrict__ xproj,     // [T*B][4H]
              const __half* __restrict__ whh_hi,   // [4H][1024] this layer
              const float* __restrict__ c0l,       // [B][H]
              __half* __restrict__ yaug,           // [T*B][2048] hi|lo
              const __half* __restrict__ h0aug,    // [B][2048] hi
              float* __restrict__ hs_out, float* __restrict__ cs_out) {
    extern __shared__ char dsm[];
    __shared__ float sg[4][32][8];
    __shared__ unsigned s_base;

    const int tid  = threadIdx.x;
    const int blk  = blockIdx.x;
    const int n0   = blk * 8;
    const int wid  = tid >> 5;
    const int lane = tid & 31;
    const int l7   = lane & 7;
    const int l16  = lane >> 4;
    const int g2   = (lane >> 3) & 3;
    const int gid  = lane >> 2;
    const int tig  = lane & 3;
    const int mt   = wid >> 2;          // batch half
    const int nt   = wid & 3;           // gate
    const int b2   = tid >> 3;          // phase2 batch
    const int u2   = tid & 7;           // phase2 unit
    const uint32_t smb = smem_u32(dsm);
    const uint32_t HBASE = 65536;       // h slot ring base

    // load W_hi into swizzled smem chunks (16 chunks of 32 rows x 64 halves)
    for (int idx = tid; idx < 4096; idx += 256) {
        int ci  = idx >> 8;
        int rr  = (idx >> 3) & 31;
        int c   = idx & 7;
        uint32_t dst = (uint32_t)(ci * 4096 + rr * 128 + ((c ^ (rr & 7)) << 4));
        int gr = (rr >> 3) * H_ + n0 + (rr & 7);
        *(float4*)(dsm + dst) =
            *(const float4*)(whh_hi + (size_t)gr * H_ + ci * 64 + c * 8);
    }

    if (tid == 0) s_base = *(volatile unsigned*)&g_flags[blk * 32];
    float c_reg = c0l[b2 * H_ + n0 + u2];
    __syncthreads();
    const unsigned base = s_base;

    const uint32_t aRow128 = (uint32_t)((mt * 16 + l7 + ((lane >> 3) & 1) * 8) * 128);
    const uint32_t bRow128 = (uint32_t)((nt * 8 + l7) * 128);

    for (int t = 0; t < T_; ++t) {
        const __half* hHi = t ? (yaug + (size_t)(t - 1) * B_ * K2) : h0aug;

        // prefetch xproj gate values (independent of h)
        const float* xp = xproj + ((size_t)t * B_ + b2) * G4H + n0 + u2;
        float xpi = __ldcg(xp);
        float xpf = __ldcg(xp + H_);
        float xpg = __ldcg(xp + 2 * H_);
        float xpo = __ldcg(xp + 3 * H_);

        auto issue_slot = [&](int i) {
            int k0 = i * 128;
            uint32_t sb = smb + HBASE + (uint32_t)((i & 3) * 8192);
            int row = tid >> 3, c = tid & 7;
            uint32_t sw = (uint32_t)(row * 128 + ((c ^ (row & 7)) << 4));
#pragma unroll
            for (int cc = 0; cc < 2; cc++)
                cp_async16(sb + cc * 4096 + sw,
                           hHi + (size_t)row * K2 + k0 + cc * 64 + c * 8);
            cp_commit();
        };

        float acc[4] = {0.f, 0.f, 0.f, 0.f};

        issue_slot(0); issue_slot(1); issue_slot(2);

#pragma unroll 1
        for (int i = 0; i < 8; i++) {
            if (i < 6)       cp_wait<2>();
            else if (i == 6) cp_wait<1>();
            else             cp_wait<0>();
            __syncthreads();
            if (i + 3 < 8) issue_slot(i + 3);

            uint32_t slotB = smb + HBASE + (uint32_t)((i & 3) * 8192);
            int ciBase = i * 2;
#pragma unroll
            for (int cc = 0; cc < 2; cc++) {
                uint32_t wHi = smb + (uint32_t)((ciBase + cc) * 4096);
                uint32_t hC  = slotB + (uint32_t)(cc * 4096);
#pragma unroll
                for (int kq2 = 0; kq2 < 2; kq2++) {
                    uint32_t bOff = bRow128 + (uint32_t)((((kq2 * 4 + g2) ^ l7)) << 4);
                    uint32_t a0[4], a1[4], bh[4];
                    ldsm4a(bh, wHi + bOff);
                    ldsm4a(a0, hC + aRow128
                               + (uint32_t)((((kq2 * 4 + l16) ^ l7)) << 4));
                    ldsm4a(a1, hC + aRow128
                               + (uint32_t)((((kq2 * 4 + 2 + l16) ^ l7)) << 4));
                    mma16816(acc, a0, bh[0], bh[1]);
                    mma16816(acc, a1, bh[2], bh[3]);
                }
            }
        }

        // gates to smem: C row = batch, col = W-row (gate nt, unit tig*2)
        sg[nt][mt * 16 + gid][tig * 2]     = acc[0];
        sg[nt][mt * 16 + gid][tig * 2 + 1] = acc[1];
        sg[nt][mt * 16 + gid + 8][tig * 2]     = acc[2];
        sg[nt][mt * 16 + gid + 8][tig * 2 + 1] = acc[3];
        __syncthreads();

        // phase 2
        float gi = sg[0][b2][u2] + xpi;
        float gf = sg[1][b2][u2] + xpf;
        float gg = sg[2][b2][u2] + xpg;
        float go = sg[3][b2][u2] + xpo;
        float iv = sigf(gi), fv = sigf(gf), gv = tanhf(gg), ov = sigf(go);
        c_reg = fv * c_reg + iv * gv;
        float h = ov * tanhf(c_reg);

        __half hh = __float2half_rn(h);
        __half hl = __float2half_rn(h - __half2float(hh));
        __half* yrow = yaug + ((size_t)t * B_ + b2) * K2 + n0 + u2;
        yrow[0]    = hh;
        yrow[1024] = hl;
        if (t == T_ - 1) {
            hs_out[b2 * H_ + n0 + u2] = h;
            cs_out[b2 * H_ + n0 + u2] = c_reg;
        }

        // distributed barrier: publish own flag, all blocks poll all flags
        __syncthreads();
        unsigned tgt = base + (unsigned)(t + 1);
        if (tid == 0) {
            __threadfence();
            *(volatile unsigned*)&g_flags[blk * 32] = tgt;
        }
        if (wid == 0) {
            volatile unsigned* fl = g_flags;
            for (;;) {
                int ok = 1;
#pragma unroll
                for (int j = 0; j < 4; j++) {
                    unsigned v = fl[(lane + 32 * j) * 32];
                    if ((int)(v - tgt) < 0) ok = 0;
                }
                if (__all_sync(0xffffffffu, ok)) break;
                __nanosleep(16);
            }
            __threadfence();
        }
        __syncthreads();
    }
}

// ---------------------------------------------------------------------------
// Launch
// ---------------------------------------------------------------------------
extern "C" void kernel_launch(void* const* d_in, const int* in_sizes, int n_in,
                              void* d_out, int out_size) {
    const int*   input = (const int*)d_in[0];
    const float* h0    = (const float*)d_in[1];
    const float* c0    = (const float*)d_in[2];
    const float* emb   = (const float*)d_in[3];
    const float* W_ih  = (const float*)d_in[4];
    const float* W_hh  = (const float*)d_in[5];
    const float* b_ih  = (const float*)d_in[6];
    const float* b_hh  = (const float*)d_in[7];
    const float* dec_W = (const float*)d_in[8];
    const float* dec_b = (const float*)d_in[9];
    float* out = (float*)d_out;

    void* p;
    cudaGetSymbolAddress(&p, g_xproj);  float* xproj = (float*)p;
    cudaGetSymbolAddress(&p, g_embaug); __half* embaug = (__half*)p;
    cudaGetSymbolAddress(&p, g_y0aug);  __half* y0aug = (__half*)p;
    cudaGetSymbolAddress(&p, g_y1aug);  __half* y1aug = (__half*)p;
    cudaGetSymbolAddress(&p, g_augwih); __half* augwih = (__half*)p;
    cudaGetSymbolAddress(&p, g_augdec); __half* augdec = (__half*)p;
    cudaGetSymbolAddress(&p, g_whhaug); __half* whhaug = (__half*)p;
    cudaGetSymbolAddress(&p, g_h0aug);  __half* h0aug = (__half*)p;

    cudaFuncSetAttribute(gemm_fp16_mma,
                         cudaFuncAttributeMaxDynamicSharedMemorySize, GEMM_SMEM);
    cudaFuncSetAttribute(lstm_mma,
                         cudaFuncAttributeMaxDynamicSharedMemorySize, LSTM_SMEM);

    // 1) embedding (fused aug) + weight augmentations
    embed_aug_kernel<<<TB, 256>>>(input, emb, embaug);
    augw_kernel<<<V_, 256>>>(dec_W, augdec);
    augw_kernel<<<G4H, 256>>>(W_ih, augwih);
    augw_kernel<<<G4H, 256>>>(W_ih + (size_t)G4H * E_, augwih + (size_t)G4H * K2);
    whh_aug_kernel<<<L_ * G4H, 256>>>(W_hh, whhaug);

    const size_t D0 = (size_t)TB * V_;
    const size_t BH = (size_t)B_ * H_;

    for (int l = 0; l < L_; ++l) {
        const __half* ain = l ? y0aug : embaug;
        __half*       yo  = l ? y1aug : y0aug;

        // 2) fp16 tensor-core input projection (A already in aug layout)
        gemm_fp16_mma<<<(G4H / 256) * 32, 256, GEMM_SMEM>>>(
            ain, augwih + (size_t)l * G4H * K2,
            b_ih + (size_t)l * G4H, b_hh + (size_t)l * G4H,
            xproj, K2, G4H);

        // 3) recurrence (persistent, mma.sync)
        h0_aug_kernel<<<B_, 256>>>(h0 + (size_t)l * BH, h0aug);
        lstm_mma<<<NBLK, 256, LSTM_SMEM>>>(
            xproj, whhaug + (size_t)l * G4H * H_,
            c0 + (size_t)l * BH, yo, h0aug,
            out + D0 + (size_t)l * BH,
            out + D0 + (size_t)L_ * BH + (size_t)l * BH);
    }

    // 4) decoder
    gemm_fp16_mma<<<(V_ / 256) * 32, 256, GEMM_SMEM>>>(
        y1aug, augdec, dec_b, nullptr, out, K2, V_);
}

// round 11
// speedup vs baseline: 1.2930x; 1.2930x over previous
#include <cuda_runtime.h>
#include <cuda_fp16.h>
#include <math.h>
#include <stdint.h>

// Problem constants
constexpr int T_ = 128, B_ = 32, L_ = 2, H_ = 1024, E_ = 1024, V_ = 32000;
constexpr int TB  = T_ * B_;     // 4096
constexpr int G4H = 4 * H_;      // 4096

constexpr int NBLK = 128;        // persistent blocks (LSTM), 8 units each

// fp16 GEMM constants
constexpr int K2 = 2048;         // 2-term augmented K (xproj)
constexpr int GEMM_SMEM = 3 * 32768;   // 3 stages x (A 16KB + B 16KB)

// LSTM smem: W_hi (16 chunks x 4KB) + 4 h slots x 8KB
constexpr int LSTM_SMEM = 16 * 4096 + 4 * 8192;   // 98304

// Scratch (device globals)
__device__ float g_xproj[TB * G4H];
__device__ alignas(256) __half g_embaug[(size_t)TB * K2];        // 16.8MB
__device__ alignas(256) __half g_y0aug[(size_t)TB * K2];         // 16.8MB
__device__ alignas(256) __half g_y1aug[(size_t)TB * K2];         // 16.8MB
__device__ alignas(256) __half g_augwih[(size_t)L_ * G4H * K2];  // 33.5MB
__device__ alignas(256) __half g_augdec[(size_t)V_ * H_];        // 65.5MB (hi only)
__device__ alignas(256) __half g_whhaug[(size_t)L_ * G4H * H_];  // 16MB (hi only)
__device__ alignas(256) __half g_h0aug[B_ * K2];                 // [32][2048] hi

// barrier state: padded per-block monotonic flags
__device__ unsigned g_flags[NBLK * 32];

// ---------------------------------------------------------------------------
// Embedding gather + fp16 hi/lo split: out[tb] = [hi(emb[v]) | lo(emb[v])]
// ---------------------------------------------------------------------------
__global__ void embed_aug_kernel(const int* __restrict__ idx,
                                 const float* __restrict__ emb,
                                 __half* __restrict__ out) {
    int tb = blockIdx.x;
    int v  = idx[tb];
    int k4 = threadIdx.x << 2;
    float4 x = *(const float4*)(emb + (size_t)v * E_ + k4);
    float xs[4] = {x.x, x.y, x.z, x.w};
    __half h[4], l[4];
#pragma unroll
    for (int j = 0; j < 4; j++) {
        h[j] = __float2half_rn(xs[j]);
        l[j] = __float2half_rn(xs[j] - __half2float(h[j]));
    }
    unsigned long long hv, lv;
    unsigned short* hp = (unsigned short*)&hv;
    unsigned short* lp = (unsigned short*)&lv;
#pragma unroll
    for (int j = 0; j < 4; j++) {
        hp[j] = *(unsigned short*)&h[j];
        lp[j] = *(unsigned short*)&l[j];
    }
    __half* base = out + (size_t)tb * K2 + k4;
    *(unsigned long long*)(base)        = hv;
    *(unsigned long long*)(base + 1024) = lv;
}

// ---------------------------------------------------------------------------
// Weight augmentation: fp32 [rows][1024] -> fp16 [rows][2048] = [hi|hi]
// ---------------------------------------------------------------------------
__global__ void augw_kernel(const float* __restrict__ in,
                            __half* __restrict__ out) {
    int r  = blockIdx.x;
    int k4 = threadIdx.x << 2;
    float4 x = *(const float4*)(in + (size_t)r * 1024 + k4);
    __half h[4] = {__float2half_rn(x.x), __float2half_rn(x.y),
                   __float2half_rn(x.z), __float2half_rn(x.w)};
    unsigned long long hv;
    unsigned short* hp = (unsigned short*)&hv;
#pragma unroll
    for (int j = 0; j < 4; j++) hp[j] = *(unsigned short*)&h[j];
    __half* base = out + (size_t)r * K2 + k4;
    *(unsigned long long*)(base)        = hv;
    *(unsigned long long*)(base + 1024) = hv;
}

// hi-plane convert: fp32 [rows][1024] -> fp16 [rows][1024]
__global__ void hi_conv_kernel(const float* __restrict__ in,
                               __half* __restrict__ out) {
    int row = blockIdx.x;
    int k = threadIdx.x << 2;
    float4 v = *(const float4*)(in + (size_t)row * 1024 + k);
    __half h[4] = {__float2half_rn(v.x), __float2half_rn(v.y),
                   __float2half_rn(v.z), __float2half_rn(v.w)};
    unsigned long long hv;
    unsigned short* hp = (unsigned short*)&hv;
#pragma unroll
    for (int j = 0; j < 4; j++) hp[j] = *(unsigned short*)&h[j];
    *(unsigned long long*)(out + (size_t)row * 1024 + k) = hv;
}

// h0 -> fp16 hi into h0aug [32][2048] (hi cols only)
__global__ void h0_aug_kernel(const float* __restrict__ h0l,
                              __half* __restrict__ h0aug) {
    int b = blockIdx.x;
    int k = threadIdx.x << 2;
    float4 v = *(const float4*)(h0l + (size_t)b * H_ + k);
    __half h[4] = {__float2half_rn(v.x), __float2half_rn(v.y),
                   __float2half_rn(v.z), __float2half_rn(v.w)};
    unsigned long long hv;
    unsigned short* hp = (unsigned short*)&hv;
#pragma unroll
    for (int j = 0; j < 4; j++) hp[j] = *(unsigned short*)&h[j];
    *(unsigned long long*)(h0aug + (size_t)b * K2 + k) = hv;
}

// ---------------------------------------------------------------------------
// low-level helpers
// ---------------------------------------------------------------------------
__device__ __forceinline__ uint32_t smem_u32(const void* p) {
    uint32_t a;
    asm("{ .reg .u64 t; cvta.to.shared.u64 t, %1; cvt.u32.u64 %0, t; }"
        : "=r"(a) : "l"(p));
    return a;
}
__device__ __forceinline__ void cp_async16(uint32_t saddr, const void* gptr) {
    asm volatile("cp.async.cg.shared.global [%0], [%1], 16;\n"
                 :: "r"(saddr), "l"(gptr));
}
__device__ __forceinline__ void cp_commit() {
    asm volatile("cp.async.commit_group;\n");
}
template <int N>
__device__ __forceinline__ void cp_wait() {
    asm volatile("cp.async.wait_group %0;\n" :: "n"(N));
}
__device__ __forceinline__ void ldsm4a(uint32_t* r, uint32_t a) {
    asm volatile("ldmatrix.sync.aligned.m8n8.x4.shared.b16 {%0,%1,%2,%3},[%4];"
                 : "=r"(r[0]), "=r"(r[1]), "=r"(r[2]), "=r"(r[3]) : "r"(a));
}
__device__ __forceinline__ void mma16816(float* c, const uint32_t* a,
                                         uint32_t b0, uint32_t b1) {
    asm volatile(
        "mma.sync.aligned.m16n8k16.row.col.f32.f16.f16.f32 "
        "{%0,%1,%2,%3},{%4,%5,%6,%7},{%8,%9},{%0,%1,%2,%3};"
        : "+f"(c[0]), "+f"(c[1]), "+f"(c[2]), "+f"(c[3])
        : "r"(a[0]), "r"(a[1]), "r"(a[2]), "r"(a[3]), "r"(b0), "r"(b1));
}
__device__ __forceinline__ float sigf(float x) { return 1.f / (1.f + expf(-x)); }

// ---------------------------------------------------------------------------
// fp16 mma.sync GEMM (R9 config + lda): C[4096, N] = A[.., lda] @ B[N, K]^T
// 128x128 block tile, 64x32 warp tile, BK=64, 3-stage, 2 CTA/SM.
// grid.x = (N/128) * 32;  bm = bid & 31, bn = bid >> 5.
// ---------------------------------------------------------------------------
__global__ __launch_bounds__(256, 2)
void gemm_fp16_mma(const __half* __restrict__ A, const __half* __restrict__ B,
                   const float* __restrict__ bias1, const float* __restrict__ bias2,
                   float* __restrict__ C, int K, int lda, int ldc) {
    extern __shared__ char sm[];
    const int tid  = threadIdx.x;
    const int lane = tid & 31;
    const int wid  = tid >> 5;
    const int bm   = blockIdx.x & 31;
    const int bn   = blockIdx.x >> 5;
    const int wm   = wid >> 2;
    const int wn   = wid & 3;
    const uint32_t smb = smem_u32(sm);
    const int KT = K >> 6;

    const __half* Ag = A + (size_t)(bm * 128) * lda;
    const __half* Bg = B + (size_t)(bn * 128) * K;

    auto issue = [&](int kt, int st) {
        uint32_t sa = smb + st * 32768;
#pragma unroll
        for (int j = 0; j < 8; j++) {
            int id  = tid + (j & 3) * 256;
            int row = id >> 3, c = id & 7;
            uint32_t dst = sa + (j < 4 ? 0u : 16384u)
                         + (uint32_t)(row * 128 + ((c ^ (row & 7)) << 4));
            const __half* src = (j < 4)
                ? Ag + (size_t)row * lda + kt * 64 + c * 8
                : Bg + (size_t)row * K   + kt * 64 + c * 8;
            cp_async16(dst, src);
        }
        cp_commit();
    };

    float acc[4][4][4];
#pragma unroll
    for (int i = 0; i < 4; i++)
#pragma unroll
        for (int j = 0; j < 4; j++)
#pragma unroll
            for (int k = 0; k < 4; k++) acc[i][j][k] = 0.f;

    issue(0, 0);
    issue(1, 1);

    const int l7  = lane & 7;
    const int l8  = (lane >> 3) & 1;
    const int l16 = lane >> 4;

    uint32_t aRow[4], bRowP[2];
#pragma unroll
    for (int mt = 0; mt < 4; mt++)
        aRow[mt] = (uint32_t)((wm * 64 + mt * 16 + l7 + l8 * 8) * 128);
#pragma unroll
    for (int ntp = 0; ntp < 2; ntp++)
        bRowP[ntp] = (uint32_t)(16384 + (wn * 32 + ntp * 16 + l16 * 8 + l7) * 128);

    for (int kt = 0; kt < KT; kt++) {
        if (kt + 1 < KT) cp_wait<1>(); else cp_wait<0>();
        __syncthreads();
        if (kt + 2 < KT) issue(kt + 2, (kt + 2) % 3);

        uint32_t st = smb + (kt % 3) * 32768;
#pragma unroll
        for (int kq = 0; kq < 4; kq++) {
            uint32_t aF[4][4], bQ[2][4];
            uint32_t ach = (uint32_t)((((kq * 2 + l16) ^ l7)) << 4);
#pragma unroll
            for (int mt = 0; mt < 4; mt++)
                ldsm4a(aF[mt], st + aRow[mt] + ach);
            uint32_t bch = (uint32_t)((((kq * 2 + l8) ^ l7)) << 4);
            ldsm4a(bQ[0], st + bRowP[0] + bch);
            ldsm4a(bQ[1], st + bRowP[1] + bch);
#pragma unroll
            for (int mt = 0; mt < 4; mt++)
#pragma unroll
                for (int nt = 0; nt < 4; nt++)
                    mma16816(acc[mt][nt], aF[mt],
                             bQ[nt >> 1][(nt & 1) * 2],
                             bQ[nt >> 1][(nt & 1) * 2 + 1]);
        }
    }

    const int gid = lane >> 2, tig = lane & 3;
#pragma unroll
    for (int mt = 0; mt < 4; mt++) {
        int row0 = bm * 128 + wm * 64 + mt * 16 + gid;
#pragma unroll
        for (int nt = 0; nt < 4; nt++) {
            int col = bn * 128 + wn * 32 + nt * 8 + tig * 2;
            float b0 = bias1 ? bias1[col] : 0.f;
            float b1 = bias1 ? bias1[col + 1] : 0.f;
            if (bias2) { b0 += bias2[col]; b1 += bias2[col + 1]; }
            *(float2*)(C + (size_t)row0 * ldc + col) =
                make_float2(acc[mt][nt][0] + b0, acc[mt][nt][1] + b1);
            *(float2*)(C + (size_t)(row0 + 8) * ldc + col) =
                make_float2(acc[mt][nt][2] + b0, acc[mt][nt][3] + b1);
        }
    }
}

// ---------------------------------------------------------------------------
// Persistent LSTM: gates = h_hi @ W_hi^T.
// h stream reads straight from yaug rows (stride K2); t=0 from h0aug.
// Output h written as [hi|lo] row of yaug (GEMM-A layout).
// ---------------------------------------------------------------------------
__global__ __launch_bounds__(256, 1)
void lstm_mma(const float* __restrict__ xproj,     // [T*B][4H]
              const __half* __restrict__ whh_hi,   // [4H][1024] this layer
              const float* __restrict__ c0l,       // [B][H]
              __half* __restrict__ yaug,           // [T*B][2048] hi|lo
              const __half* __restrict__ h0aug,    // [B][2048] hi
              float* __restrict__ hs_out, float* __restrict__ cs_out) {
    extern __shared__ char dsm[];
    __shared__ float sg[4][32][8];
    __shared__ unsigned s_base;

    const int tid  = threadIdx.x;
    const int blk  = blockIdx.x;
    const int n0   = blk * 8;
    const int wid  = tid >> 5;
    const int lane = tid & 31;
    const int l7   = lane & 7;
    const int l16  = lane >> 4;
    const int g2   = (lane >> 3) & 3;
    const int gid  = lane >> 2;
    const int tig  = lane & 3;
    const int mt   = wid >> 2;          // batch half
    const int nt   = wid & 3;           // gate
    const int b2   = tid >> 3;          // phase2 batch
    const int u2   = tid & 7;           // phase2 unit
    const uint32_t smb = smem_u32(dsm);
    const uint32_t HBASE = 65536;       // h slot ring base

    // load W_hi into swizzled smem chunks (16 chunks of 32 rows x 64 halves)
    for (int idx = tid; idx < 4096; idx += 256) {
        int ci  = idx >> 8;
        int rr  = (idx >> 3) & 31;
        int c   = idx & 7;
        uint32_t dst = (uint32_t)(ci * 4096 + rr * 128 + ((c ^ (rr & 7)) << 4));
        int gr = (rr >> 3) * H_ + n0 + (rr & 7);
        *(float4*)(dsm + dst) =
            *(const float4*)(whh_hi + (size_t)gr * H_ + ci * 64 + c * 8);
    }

    if (tid == 0) s_base = *(volatile unsigned*)&g_flags[blk * 32];
    float c_reg = c0l[b2 * H_ + n0 + u2];
    __syncthreads();
    const unsigned base = s_base;

    const uint32_t aRow128 = (uint32_t)((mt * 16 + l7 + ((lane >> 3) & 1) * 8) * 128);
    const uint32_t bRow128 = (uint32_t)((nt * 8 + l7) * 128);

    for (int t = 0; t < T_; ++t) {
        const __half* hHi = t ? (yaug + (size_t)(t - 1) * B_ * K2) : h0aug;

        // prefetch xproj gate values (independent of h)
        const float* xp = xproj + ((size_t)t * B_ + b2) * G4H + n0 + u2;
        float xpi = __ldcg(xp);
        float xpf = __ldcg(xp + H_);
        float xpg = __ldcg(xp + 2 * H_);
        float xpo = __ldcg(xp + 3 * H_);

        auto issue_slot = [&](int i) {
            int k0 = i * 128;
            uint32_t sb = smb + HBASE + (uint32_t)((i & 3) * 8192);
            int row = tid >> 3, c = tid & 7;
            uint32_t sw = (uint32_t)(row * 128 + ((c ^ (row & 7)) << 4));
#pragma unroll
            for (int cc = 0; cc < 2; cc++)
                cp_async16(sb + cc * 4096 + sw,
                           hHi + (size_t)row * K2 + k0 + cc * 64 + c * 8);
            cp_commit();
        };

        float acc[4] = {0.f, 0.f, 0.f, 0.f};

        issue_slot(0); issue_slot(1); issue_slot(2);

#pragma unroll 1
        for (int i = 0; i < 8; i++) {
            if (i < 6)       cp_wait<2>();
            else if (i == 6) cp_wait<1>();
            else             cp_wait<0>();
            __syncthreads();
            if (i + 3 < 8) issue_slot(i + 3);

            uint32_t slotB = smb + HBASE + (uint32_t)((i & 3) * 8192);
            int ciBase = i * 2;
#pragma unroll
            for (int cc = 0; cc < 2; cc++) {
                uint32_t wHi = smb + (uint32_t)((ciBase + cc) * 4096);
                uint32_t hC  = slotB + (uint32_t)(cc * 4096);
#pragma unroll
                for (int kq2 = 0; kq2 < 2; kq2++) {
                    uint32_t bOff = bRow128 + (uint32_t)((((kq2 * 4 + g2) ^ l7)) << 4);
                    uint32_t a0[4], a1[4], bh[4];
                    ldsm4a(bh, wHi + bOff);
                    ldsm4a(a0, hC + aRow128
                               + (uint32_t)((((kq2 * 4 + l16) ^ l7)) << 4));
                    ldsm4a(a1, hC + aRow128
                               + (uint32_t)((((kq2 * 4 + 2 + l16) ^ l7)) << 4));
                    mma16816(acc, a0, bh[0], bh[1]);
                    mma16816(acc, a1, bh[2], bh[3]);
                }
            }
        }

        // gates to smem: C row = batch, col = W-row (gate nt, unit tig*2)
        sg[nt][mt * 16 + gid][tig * 2]     = acc[0];
        sg[nt][mt * 16 + gid][tig * 2 + 1] = acc[1];
        sg[nt][mt * 16 + gid + 8][tig * 2]     = acc[2];
        sg[nt][mt * 16 + gid + 8][tig * 2 + 1] = acc[3];
        __syncthreads();

        // phase 2
        float gi = sg[0][b2][u2] + xpi;
        float gf = sg[1][b2][u2] + xpf;
        float gg = sg[2][b2][u2] + xpg;
        float go = sg[3][b2][u2] + xpo;
        float iv = sigf(gi), fv = sigf(gf), gv = tanhf(gg), ov = sigf(go);
        c_reg = fv * c_reg + iv * gv;
        float h = ov * tanhf(c_reg);

        __half hh = __float2half_rn(h);
        __half hl = __float2half_rn(h - __half2float(hh));
        __half* yrow = yaug + ((size_t)t * B_ + b2) * K2 + n0 + u2;
        yrow[0]    = hh;
        yrow[1024] = hl;
        if (t == T_ - 1) {
            hs_out[b2 * H_ + n0 + u2] = h;
            cs_out[b2 * H_ + n0 + u2] = c_reg;
        }

        // distributed barrier: publish own flag, all blocks poll all flags
        __syncthreads();
        unsigned tgt = base + (unsigned)(t + 1);
        if (tid == 0) {
            __threadfence();
            *(volatile unsigned*)&g_flags[blk * 32] = tgt;
        }
        if (wid == 0) {
            volatile unsigned* fl = g_flags;
            for (;;) {
                int ok = 1;
#pragma unroll
                for (int j = 0; j < 4; j++) {
                    unsigned v = fl[(lane + 32 * j) * 32];
                    if ((int)(v - tgt) < 0) ok = 0;
                }
                if (__all_sync(0xffffffffu, ok)) break;
                __nanosleep(16);
            }
            __threadfence();
        }
        __syncthreads();
    }
}

// ---------------------------------------------------------------------------
// Launch
// ---------------------------------------------------------------------------
extern "C" void kernel_launch(void* const* d_in, const int* in_sizes, int n_in,
                              void* d_out, int out_size) {
    const int*   input = (const int*)d_in[0];
    const float* h0    = (const float*)d_in[1];
    const float* c0    = (const float*)d_in[2];
    const float* emb   = (const float*)d_in[3];
    const float* W_ih  = (const float*)d_in[4];
    const float* W_hh  = (const float*)d_in[5];
    const float* b_ih  = (const float*)d_in[6];
    const float* b_hh  = (const float*)d_in[7];
    const float* dec_W = (const float*)d_in[8];
    const float* dec_b = (const float*)d_in[9];
    float* out = (float*)d_out;

    void* p;
    cudaGetSymbolAddress(&p, g_xproj);  float* xproj = (float*)p;
    cudaGetSymbolAddress(&p, g_embaug); __half* embaug = (__half*)p;
    cudaGetSymbolAddress(&p, g_y0aug);  __half* y0aug = (__half*)p;
    cudaGetSymbolAddress(&p, g_y1aug);  __half* y1aug = (__half*)p;
    cudaGetSymbolAddress(&p, g_augwih); __half* augwih = (__half*)p;
    cudaGetSymbolAddress(&p, g_augdec); __half* augdec = (__half*)p;
    cudaGetSymbolAddress(&p, g_whhaug); __half* whhaug = (__half*)p;
    cudaGetSymbolAddress(&p, g_h0aug);  __half* h0aug = (__half*)p;

    cudaFuncSetAttribute(gemm_fp16_mma,
                         cudaFuncAttributeMaxDynamicSharedMemorySize, GEMM_SMEM);
    cudaFuncSetAttribute(lstm_mma,
                         cudaFuncAttributeMaxDynamicSharedMemorySize, LSTM_SMEM);

    // 1) embedding (fused aug) + weight conversions
    embed_aug_kernel<<<TB, 256>>>(input, emb, embaug);
    hi_conv_kernel<<<V_, 256>>>(dec_W, augdec);                 // hi plane only
    augw_kernel<<<G4H, 256>>>(W_ih, augwih);                    // [hi|hi]
    augw_kernel<<<G4H, 256>>>(W_ih + (size_t)G4H * E_, augwih + (size_t)G4H * K2);
    hi_conv_kernel<<<L_ * G4H, 256>>>(W_hh, whhaug);

    const size_t D0 = (size_t)TB * V_;
    const size_t BH = (size_t)B_ * H_;

    for (int l = 0; l < L_; ++l) {
        const __half* ain = l ? y0aug : embaug;
        __half*       yo  = l ? y1aug : y0aug;

        // 2) input projection: A=[hi|lo] (K=2048), B=W_ih [hi|hi]
        gemm_fp16_mma<<<(G4H / 128) * 32, 256, GEMM_SMEM>>>(
            ain, augwih + (size_t)l * G4H * K2,
            b_ih + (size_t)l * G4H, b_hh + (size_t)l * G4H,
            xproj, K2, K2, G4H);

        // 3) recurrence (persistent, mma.sync)
        h0_aug_kernel<<<B_, 256>>>(h0 + (size_t)l * BH, h0aug);
        lstm_mma<<<NBLK, 256, LSTM_SMEM>>>(
            xproj, whhaug + (size_t)l * G4H * H_,
            c0 + (size_t)l * BH, yo, h0aug,
            out + D0 + (size_t)l * BH,
            out + D0 + (size_t)L_ * BH + (size_t)l * BH);
    }

    // 4) decoder: hi-only (K=1024, A rows strided by 2048)
    gemm_fp16_mma<<<(V_ / 128) * 32, 256, GEMM_SMEM>>>(
        y1aug, augdec, dec_b, nullptr, out, H_, K2, V_);
}

// round 12
// speedup vs baseline: 1.5881x; 1.2282x over previous
#include <cuda_runtime.h>
#include <cuda_fp16.h>
#include <math.h>
#include <stdint.h>

// Problem constants
constexpr int T_ = 128, B_ = 32, L_ = 2, H_ = 1024, E_ = 1024, V_ = 32000;
constexpr int TB  = T_ * B_;     // 4096
constexpr int G4H = 4 * H_;      // 4096
constexpr int BH  = B_ * H_;     // 32768

constexpr int NBLK = 128;        // persistent blocks, 8 units x 2 layers each

// fp16 GEMM constants
constexpr int K2 = 2048;
constexpr int GEMM_SMEM = 3 * 32768;

// Fused LSTM smem: 3 W slices (64KB each) + 2 streams x 2 slots x 8KB
constexpr int SLOTS_OFF = 196608;
constexpr int LSTM_SMEM = 229376;     // 192KB + 32KB (sg overlays slots)

// Scratch (device globals)
__device__ float g_xproj[TB * G4H];                              // layer0 only
__device__ alignas(256) __half g_embaug[(size_t)TB * K2];        // 16.8MB
__device__ alignas(256) __half g_y0[(size_t)TB * H_];            // 8.4MB hi
__device__ alignas(256) __half g_y1[(size_t)TB * H_];            // 8.4MB hi
__device__ alignas(256) __half g_augwih[(size_t)G4H * K2];       // l0 [hi|hi]
__device__ alignas(256) __half g_wih1hi[(size_t)G4H * H_];       // l1 hi plane
__device__ alignas(256) __half g_augdec[(size_t)V_ * H_];        // hi plane
__device__ alignas(256) __half g_whhaug[(size_t)L_ * G4H * H_];  // hi planes
__device__ alignas(256) __half g_h0aug[L_ * B_ * H_];            // [2][B][1024] hi

// barrier state: padded per-block monotonic flags
__device__ unsigned g_flags[NBLK * 32];

// ---------------------------------------------------------------------------
// Embedding gather + fp16 hi/lo split (layer0 GEMM A operand)
// ---------------------------------------------------------------------------
__global__ void embed_aug_kernel(const int* __restrict__ idx,
                                 const float* __restrict__ emb,
                                 __half* __restrict__ out) {
    int tb = blockIdx.x;
    int v  = idx[tb];
    int k4 = threadIdx.x << 2;
    float4 x = *(const float4*)(emb + (size_t)v * E_ + k4);
    float xs[4] = {x.x, x.y, x.z, x.w};
    __half h[4], l[4];
#pragma unroll
    for (int j = 0; j < 4; j++) {
        h[j] = __float2half_rn(xs[j]);
        l[j] = __float2half_rn(xs[j] - __half2float(h[j]));
    }
    unsigned long long hv, lv;
    unsigned short* hp = (unsigned short*)&hv;
    unsigned short* lp = (unsigned short*)&lv;
#pragma unroll
    for (int j = 0; j < 4; j++) {
        hp[j] = *(unsigned short*)&h[j];
        lp[j] = *(unsigned short*)&l[j];
    }
    __half* base = out + (size_t)tb * K2 + k4;
    *(unsigned long long*)(base)        = hv;
    *(unsigned long long*)(base + 1024) = lv;
}

// Weight augmentation: fp32 [rows][1024] -> fp16 [rows][2048] = [hi|hi]
__global__ void augw_kernel(const float* __restrict__ in,
                            __half* __restrict__ out) {
    int r  = blockIdx.x;
    int k4 = threadIdx.x << 2;
    float4 x = *(const float4*)(in + (size_t)r * 1024 + k4);
    __half h[4] = {__float2half_rn(x.x), __float2half_rn(x.y),
                   __float2half_rn(x.z), __float2half_rn(x.w)};
    unsigned long long hv;
    unsigned short* hp = (unsigned short*)&hv;
#pragma unroll
    for (int j = 0; j < 4; j++) hp[j] = *(unsigned short*)&h[j];
    __half* base = out + (size_t)r * K2 + k4;
    *(unsigned long long*)(base)        = hv;
    *(unsigned long long*)(base + 1024) = hv;
}

// hi-plane convert: fp32 [rows][1024] -> fp16 [rows][1024]
__global__ void hi_conv_kernel(const float* __restrict__ in,
                               __half* __restrict__ out) {
    int row = blockIdx.x;
    int k = threadIdx.x << 2;
    float4 v = *(const float4*)(in + (size_t)row * 1024 + k);
    __half h[4] = {__float2half_rn(v.x), __float2half_rn(v.y),
                   __float2half_rn(v.z), __float2half_rn(v.w)};
    unsigned long long hv;
    unsigned short* hp = (unsigned short*)&hv;
#pragma unroll
    for (int j = 0; j < 4; j++) hp[j] = *(unsigned short*)&h[j];
    *(unsigned long long*)(out + (size_t)row * 1024 + k) = hv;
}

// ---------------------------------------------------------------------------
// low-level helpers
// ---------------------------------------------------------------------------
__device__ __forceinline__ uint32_t smem_u32(const void* p) {
    uint32_t a;
    asm("{ .reg .u64 t; cvta.to.shared.u64 t, %1; cvt.u32.u64 %0, t; }"
        : "=r"(a) : "l"(p));
    return a;
}
__device__ __forceinline__ void cp_async16(uint32_t saddr, const void* gptr) {
    asm volatile("cp.async.cg.shared.global [%0], [%1], 16;\n"
                 :: "r"(saddr), "l"(gptr));
}
__device__ __forceinline__ void cp_commit() {
    asm volatile("cp.async.commit_group;\n");
}
template <int N>
__device__ __forceinline__ void cp_wait() {
    asm volatile("cp.async.wait_group %0;\n" :: "n"(N));
}
__device__ __forceinline__ void ldsm4a(uint32_t* r, uint32_t a) {
    asm volatile("ldmatrix.sync.aligned.m8n8.x4.shared.b16 {%0,%1,%2,%3},[%4];"
                 : "=r"(r[0]), "=r"(r[1]), "=r"(r[2]), "=r"(r[3]) : "r"(a));
}
__device__ __forceinline__ void mma16816(float* c, const uint32_t* a,
                                         uint32_t b0, uint32_t b1) {
    asm volatile(
        "mma.sync.aligned.m16n8k16.row.col.f32.f16.f16.f32 "
        "{%0,%1,%2,%3},{%4,%5,%6,%7},{%8,%9},{%0,%1,%2,%3};"
        : "+f"(c[0]), "+f"(c[1]), "+f"(c[2]), "+f"(c[3])
        : "r"(a[0]), "r"(a[1]), "r"(a[2]), "r"(a[3]), "r"(b0), "r"(b1));
}
__device__ __forceinline__ float sigf(float x) { return 1.f / (1.f + expf(-x)); }

// ---------------------------------------------------------------------------
// fp16 mma.sync GEMM (proven R9/R11 config): C = A[.., lda] @ B[N,K]^T + bias
// ---------------------------------------------------------------------------
__global__ __launch_bounds__(256, 2)
void gemm_fp16_mma(const __half* __restrict__ A, const __half* __restrict__ B,
                   const float* __restrict__ bias1, const float* __restrict__ bias2,
                   float* __restrict__ C, int K, int lda, int ldc) {
    extern __shared__ char sm[];
    const int tid  = threadIdx.x;
    const int lane = tid & 31;
    const int wid  = tid >> 5;
    const int bm   = blockIdx.x & 31;
    const int bn   = blockIdx.x >> 5;
    const int wm   = wid >> 2;
    const int wn   = wid & 3;
    const uint32_t smb = smem_u32(sm);
    const int KT = K >> 6;

    const __half* Ag = A + (size_t)(bm * 128) * lda;
    const __half* Bg = B + (size_t)(bn * 128) * K;

    auto issue = [&](int kt, int st) {
        uint32_t sa = smb + st * 32768;
#pragma unroll
        for (int j = 0; j < 8; j++) {
            int id  = tid + (j & 3) * 256;
            int row = id >> 3, c = id & 7;
            uint32_t dst = sa + (j < 4 ? 0u : 16384u)
                         + (uint32_t)(row * 128 + ((c ^ (row & 7)) << 4));
            const __half* src = (j < 4)
                ? Ag + (size_t)row * lda + kt * 64 + c * 8
                : Bg + (size_t)row * K   + kt * 64 + c * 8;
            cp_async16(dst, src);
        }
        cp_commit();
    };

    float acc[4][4][4];
#pragma unroll
    for (int i = 0; i < 4; i++)
#pragma unroll
        for (int j = 0; j < 4; j++)
#pragma unroll
            for (int k = 0; k < 4; k++) acc[i][j][k] = 0.f;

    issue(0, 0);
    issue(1, 1);

    const int l7  = lane & 7;
    const int l8  = (lane >> 3) & 1;
    const int l16 = lane >> 4;

    uint32_t aRow[4], bRowP[2];
#pragma unroll
    for (int mt = 0; mt < 4; mt++)
        aRow[mt] = (uint32_t)((wm * 64 + mt * 16 + l7 + l8 * 8) * 128);
#pragma unroll
    for (int ntp = 0; ntp < 2; ntp++)
        bRowP[ntp] = (uint32_t)(16384 + (wn * 32 + ntp * 16 + l16 * 8 + l7) * 128);

    for (int kt = 0; kt < KT; kt++) {
        if (kt + 1 < KT) cp_wait<1>(); else cp_wait<0>();
        __syncthreads();
        if (kt + 2 < KT) issue(kt + 2, (kt + 2) % 3);

        uint32_t st = smb + (kt % 3) * 32768;
#pragma unroll
        for (int kq = 0; kq < 4; kq++) {
            uint32_t aF[4][4], bQ[2][4];
            uint32_t ach = (uint32_t)((((kq * 2 + l16) ^ l7)) << 4);
#pragma unroll
            for (int mt = 0; mt < 4; mt++)
                ldsm4a(aF[mt], st + aRow[mt] + ach);
            uint32_t bch = (uint32_t)((((kq * 2 + l8) ^ l7)) << 4);
            ldsm4a(bQ[0], st + bRowP[0] + bch);
            ldsm4a(bQ[1], st + bRowP[1] + bch);
#pragma unroll
            for (int mt = 0; mt < 4; mt++)
#pragma unroll
                for (int nt = 0; nt < 4; nt++)
                    mma16816(acc[mt][nt], aF[mt],
                             bQ[nt >> 1][(nt & 1) * 2],
                             bQ[nt >> 1][(nt & 1) * 2 + 1]);
        }
    }

    const int gid = lane >> 2, tig = lane & 3;
#pragma unroll
    for (int mt = 0; mt < 4; mt++) {
        int row0 = bm * 128 + wm * 64 + mt * 16 + gid;
#pragma unroll
        for (int nt = 0; nt < 4; nt++) {
            int col = bn * 128 + wn * 32 + nt * 8 + tig * 2;
            float b0 = bias1 ? bias1[col] : 0.f;
            float b1 = bias1 ? bias1[col + 1] : 0.f;
            if (bias2) { b0 += bias2[col]; b1 += bias2[col + 1]; }
            *(float2*)(C + (size_t)row0 * ldc + col) =
                make_float2(acc[mt][nt][0] + b0, acc[mt][nt][1] + b1);
            *(float2*)(C + (size_t)(row0 + 8) * ldc + col) =
                make_float2(acc[mt][nt][2] + b0, acc[mt][nt][3] + b1);
        }
    }
}

// ---------------------------------------------------------------------------
// Fused 2-layer persistent LSTM, wavefront pipeline.
// Round r (0..128): layer0 computes t=r (r<128); layer1 computes t=r-1 (r>=1).
// Layer1 gates = y0[t] @ W_ih1^T + y1[t-1] @ W_hh1^T + b1 (x-proj in-kernel).
// Block owns 8 hidden units of BOTH layers (32 gate rows per W matrix).
// smem: W_hh0 | W_ih1 | W_hh1 (64KB each) + 2 streams x 2 slots x 8KB.
// ---------------------------------------------------------------------------
__global__ __launch_bounds__(256, 1)
void lstm_fused(const float* __restrict__ xproj,    // [T*B][4H] layer0
                const __half* __restrict__ w0,      // W_hh0 hi [4H][1024]
                const __half* __restrict__ w1x,     // W_ih1 hi [4H][1024]
                const __half* __restrict__ w1h,     // W_hh1 hi [4H][1024]
                const float* __restrict__ c0,       // [2][B][H]
                const float* __restrict__ b_ih,     // [2][4H]
                const float* __restrict__ b_hh,     // [2][4H]
                const __half* __restrict__ h0a,     // [2][B][1024] hi
                __half* __restrict__ y0,            // [T*B][1024] hi
                __half* __restrict__ y1,            // [T*B][1024] hi
                float* __restrict__ outs) {         // hs[2][B][H], cs[2][B][H]
    extern __shared__ char dsm[];
    __shared__ unsigned s_base;

    const int tid  = threadIdx.x;
    const int blk  = blockIdx.x;
    const int n0   = blk * 8;
    const int wid  = tid >> 5;
    const int lane = tid & 31;
    const int l7   = lane & 7;
    const int l16  = lane >> 4;
    const int g2   = (lane >> 3) & 3;
    const int gid  = lane >> 2;
    const int tig  = lane & 3;
    const int mt   = wid >> 2;          // batch half
    const int nt   = wid & 3;           // gate
    const int b2   = tid >> 3;          // phase2 batch
    const int u2   = tid & 7;           // phase2 unit
    const uint32_t smb = smem_u32(dsm);

    // load 3 weight slices (32 rows x 1024 each) into swizzled chunk layout
    for (int idx = tid; idx < 3 * 4096; idx += 256) {
        int m   = idx >> 12;
        int rem = idx & 4095;
        int ci  = rem >> 8;
        int rr  = (rem >> 3) & 31;
        int c   = rem & 7;
        uint32_t dst = (uint32_t)(m * 65536 + ci * 4096 + rr * 128
                                  + ((c ^ (rr & 7)) << 4));
        int gr = (rr >> 3) * H_ + n0 + (rr & 7);
        const __half* src = (m == 0 ? w0 : (m == 1 ? w1x : w1h))
                          + (size_t)gr * H_ + ci * 64 + c * 8;
        *(float4*)(dsm + dst) = *(const float4*)src;
    }

    if (tid == 0) s_base = *(volatile unsigned*)&g_flags[blk * 32];

    float c_reg0 = c0[b2 * H_ + n0 + u2];
    float c_reg1 = c0[BH + b2 * H_ + n0 + u2];
    float bi1[4];
#pragma unroll
    for (int g = 0; g < 4; g++)
        bi1[g] = b_ih[G4H + g * H_ + n0 + u2] + b_hh[G4H + g * H_ + n0 + u2];

    __syncthreads();
    const unsigned base = s_base;

    const uint32_t aRow128 = (uint32_t)((mt * 16 + l7 + ((lane >> 3) & 1) * 8) * 128);
    const uint32_t bRow128 = (uint32_t)((nt * 8 + l7) * 128);

    for (int r = 0; r <= T_; ++r) {
        const __half* Asrc = (r == 0) ? h0a : y0 + (size_t)(r - 1) * B_ * H_;
        const __half* Bsrc = (r <= 1) ? (h0a + (size_t)B_ * H_)
                                      : y1 + (size_t)(r - 2) * B_ * H_;

        // prefetch xproj0 gate values (clamped at r=T_, discarded)
        int tx = (r < T_) ? r : (T_ - 1);
        const float* xp = xproj + ((size_t)tx * B_ + b2) * G4H + n0 + u2;
        float xpi = __ldcg(xp);
        float xpf = __ldcg(xp + H_);
        float xpg = __ldcg(xp + 2 * H_);
        float xpo = __ldcg(xp + 3 * H_);

        auto issue_slot = [&](int i) {
            int k0 = i * 128;
            int row = tid >> 3, c = tid & 7;
            uint32_t sw = (uint32_t)(row * 128 + ((c ^ (row & 7)) << 4));
            uint32_t sbA = smb + SLOTS_OFF + (uint32_t)((i & 1) * 8192);
            uint32_t sbB = sbA + 16384u;
#pragma unroll
            for (int cc = 0; cc < 2; cc++) {
                cp_async16(sbA + cc * 4096 + sw,
                           Asrc + (size_t)row * H_ + k0 + cc * 64 + c * 8);
                cp_async16(sbB + cc * 4096 + sw,
                           Bsrc + (size_t)row * H_ + k0 + cc * 64 + c * 8);
            }
            cp_commit();
        };

        float acc0[4] = {0.f, 0.f, 0.f, 0.f};
        float acc1[4] = {0.f, 0.f, 0.f, 0.f};

        issue_slot(0); issue_slot(1);

#pragma unroll 1
        for (int i = 0; i < 8; i++) {
            if (i < 7) cp_wait<1>(); else cp_wait<0>();
            __syncthreads();

            uint32_t slotA = smb + SLOTS_OFF + (uint32_t)((i & 1) * 8192);
            uint32_t slotB = slotA + 16384u;
            int ciBase = i * 2;
#pragma unroll
            for (int cc = 0; cc < 2; cc++) {
                uint32_t wB0  = smb + (uint32_t)((ciBase + cc) * 4096);
                uint32_t wB1x = wB0 + 65536u;
                uint32_t wB1h = wB0 + 131072u;
                uint32_t hA = slotA + (uint32_t)(cc * 4096);
                uint32_t hB = slotB + (uint32_t)(cc * 4096);
#pragma unroll
                for (int kq2 = 0; kq2 < 2; kq2++) {
                    uint32_t bOff = bRow128 + (uint32_t)((((kq2 * 4 + g2) ^ l7)) << 4);
                    uint32_t aO0  = (uint32_t)((((kq2 * 4 + l16) ^ l7)) << 4);
                    uint32_t aO1  = (uint32_t)((((kq2 * 4 + 2 + l16) ^ l7)) << 4);
                    uint32_t a0[4], a1[4], bb0[4], bb1[4], w[4];
                    ldsm4a(a0, hA + aRow128 + aO0);
                    ldsm4a(a1, hA + aRow128 + aO1);
                    ldsm4a(w, wB0 + bOff);
                    mma16816(acc0, a0, w[0], w[1]);
                    mma16816(acc0, a1, w[2], w[3]);
                    ldsm4a(w, wB1x + bOff);
                    mma16816(acc1, a0, w[0], w[1]);
                    mma16816(acc1, a1, w[2], w[3]);
                    ldsm4a(bb0, hB + aRow128 + aO0);
                    ldsm4a(bb1, hB + aRow128 + aO1);
                    ldsm4a(w, wB1h + bOff);
                    mma16816(acc1, bb0, w[0], w[1]);
                    mma16816(acc1, bb1, w[2], w[3]);
                }
            }
            __syncthreads();
            if (i + 2 < 8) issue_slot(i + 2);
        }

        // gates to smem (overlay on slot region; all slot reads done)
        float* sg0 = (float*)(dsm + SLOTS_OFF);
        float* sg1 = sg0 + 1024;
        {
            int row = mt * 16 + gid;
            sg0[nt * 256 + row * 8 + tig * 2]           = acc0[0];
            sg0[nt * 256 + row * 8 + tig * 2 + 1]       = acc0[1];
            sg0[nt * 256 + (row + 8) * 8 + tig * 2]     = acc0[2];
            sg0[nt * 256 + (row + 8) * 8 + tig * 2 + 1] = acc0[3];
            sg1[nt * 256 + row * 8 + tig * 2]           = acc1[0];
            sg1[nt * 256 + row * 8 + tig * 2 + 1]       = acc1[1];
            sg1[nt * 256 + (row + 8) * 8 + tig * 2]     = acc1[2];
            sg1[nt * 256 + (row + 8) * 8 + tig * 2 + 1] = acc1[3];
        }
        __syncthreads();

        // phase 2: layer 0 (t = r)
        if (r < T_) {
            float gi = sg0[0 * 256 + b2 * 8 + u2] + xpi;
            float gf = sg0[1 * 256 + b2 * 8 + u2] + xpf;
            float gg = sg0[2 * 256 + b2 * 8 + u2] + xpg;
            float go = sg0[3 * 256 + b2 * 8 + u2] + xpo;
            float iv = sigf(gi), fv = sigf(gf), gv = tanhf(gg), ov = sigf(go);
            c_reg0 = fv * c_reg0 + iv * gv;
            float h = ov * tanhf(c_reg0);
            y0[((size_t)r * B_ + b2) * H_ + n0 + u2] = __float2half_rn(h);
            if (r == T_ - 1) {
                outs[b2 * H_ + n0 + u2]          = h;        // hs[0]
                outs[2 * BH + b2 * H_ + n0 + u2] = c_reg0;   // cs[0]
            }
        }
        // phase 2: layer 1 (t = r-1)
        if (r >= 1) {
            int t = r - 1;
            float gi = sg1[0 * 256 + b2 * 8 + u2] + bi1[0];
            float gf = sg1[1 * 256 + b2 * 8 + u2] + bi1[1];
            float gg = sg1[2 * 256 + b2 * 8 + u2] + bi1[2];
            float go = sg1[3 * 256 + b2 * 8 + u2] + bi1[3];
            float iv = sigf(gi), fv = sigf(gf), gv = tanhf(gg), ov = sigf(go);
            c_reg1 = fv * c_reg1 + iv * gv;
            float h = ov * tanhf(c_reg1);
            y1[((size_t)t * B_ + b2) * H_ + n0 + u2] = __float2half_rn(h);
            if (t == T_ - 1) {
                outs[BH + b2 * H_ + n0 + u2]     = h;        // hs[1]
                outs[3 * BH + b2 * H_ + n0 + u2] = c_reg1;   // cs[1]
            }
        }

        // distributed barrier
        __syncthreads();
        unsigned tgt = base + (unsigned)(r + 1);
        if (tid == 0) {
            __threadfence();
            *(volatile unsigned*)&g_flags[blk * 32] = tgt;
        }
        if (wid == 0) {
            volatile unsigned* fl = g_flags;
            for (;;) {
                int ok = 1;
#pragma unroll
                for (int j = 0; j < 4; j++) {
                    unsigned v = fl[(lane + 32 * j) * 32];
                    if ((int)(v - tgt) < 0) ok = 0;
                }
                if (__all_sync(0xffffffffu, ok)) break;
                __nanosleep(16);
            }
            __threadfence();
        }
        __syncthreads();
    }
}

// ---------------------------------------------------------------------------
// Launch
// ---------------------------------------------------------------------------
extern "C" void kernel_launch(void* const* d_in, const int* in_sizes, int n_in,
                              void* d_out, int out_size) {
    const int*   input = (const int*)d_in[0];
    const float* h0    = (const float*)d_in[1];
    const float* c0    = (const float*)d_in[2];
    const float* emb   = (const float*)d_in[3];
    const float* W_ih  = (const float*)d_in[4];
    const float* W_hh  = (const float*)d_in[5];
    const float* b_ih  = (const float*)d_in[6];
    const float* b_hh  = (const float*)d_in[7];
    const float* dec_W = (const float*)d_in[8];
    const float* dec_b = (const float*)d_in[9];
    float* out = (float*)d_out;

    void* p;
    cudaGetSymbolAddress(&p, g_xproj);  float* xproj = (float*)p;
    cudaGetSymbolAddress(&p, g_embaug); __half* embaug = (__half*)p;
    cudaGetSymbolAddress(&p, g_y0);     __half* y0 = (__half*)p;
    cudaGetSymbolAddress(&p, g_y1);     __half* y1 = (__half*)p;
    cudaGetSymbolAddress(&p, g_augwih); __half* augwih = (__half*)p;
    cudaGetSymbolAddress(&p, g_wih1hi); __half* wih1hi = (__half*)p;
    cudaGetSymbolAddress(&p, g_augdec); __half* augdec = (__half*)p;
    cudaGetSymbolAddress(&p, g_whhaug); __half* whhaug = (__half*)p;
    cudaGetSymbolAddress(&p, g_h0aug);  __half* h0aug = (__half*)p;

    cudaFuncSetAttribute(gemm_fp16_mma,
                         cudaFuncAttributeMaxDynamicSharedMemorySize, GEMM_SMEM);
    cudaFuncSetAttribute(lstm_fused,
                         cudaFuncAttributeMaxDynamicSharedMemorySize, LSTM_SMEM);

    // 1) embedding (fused aug) + weight conversions + initial states
    embed_aug_kernel<<<TB, 256>>>(input, emb, embaug);
    hi_conv_kernel<<<V_, 256>>>(dec_W, augdec);                   // decoder hi
    augw_kernel<<<G4H, 256>>>(W_ih, augwih);                      // l0 [hi|hi]
    hi_conv_kernel<<<G4H, 256>>>(W_ih + (size_t)G4H * E_, wih1hi);// l1 hi
    hi_conv_kernel<<<L_ * G4H, 256>>>(W_hh, whhaug);              // hh hi
    hi_conv_kernel<<<L_ * B_, 256>>>(h0, h0aug);                  // h0 hi

    const size_t D0 = (size_t)TB * V_;

    // 2) layer0 input projection: A=embaug [hi|lo] K=2048
    gemm_fp16_mma<<<(G4H / 128) * 32, 256, GEMM_SMEM>>>(
        embaug, augwih, b_ih, b_hh, xproj, K2, K2, G4H);

    // 3) fused 2-layer recurrence (129 wavefront rounds)
    lstm_fused<<<NBLK, 256, LSTM_SMEM>>>(
        xproj, whhaug, wih1hi, whhaug + (size_t)G4H * H_,
        c0, b_ih, b_hh, h0aug, y0, y1, out + D0);

    // 4) decoder: hi-only (K=1024, lda=1024)
    gemm_fp16_mma<<<(V_ / 128) * 32, 256, GEMM_SMEM>>>(
        y1, augdec, dec_b, nullptr, out, H_, H_, V_);
}